// round 17
// baseline (speedup 1.0000x reference)
#include <cuda_runtime.h>
#include <cuda_bf16.h>
#include <math.h>
#include <stdint.h>

#define BATCH 32
#define TT0 2048
#define TT1 2044
#define TT2 2040
#define TT3 2034
#define N1 (BATCH*TT1)
#define N2 (BATCH*TT2)
#define N3 (BATCH*TT3)

// ---------------- scratch ----------------
__device__ __nv_bfloat16 g_xsh[(size_t)N1 * 128], g_xsl[(size_t)N1 * 128];
__device__ __nv_bfloat16 g_aH0[(size_t)N1 * 512], g_aL0[(size_t)N1 * 512];
__device__ __nv_bfloat16 g_aH1[(size_t)N1 * 512], g_aL1[(size_t)N1 * 512];
__device__ __nv_bfloat16 g_w1h[512 * 128], g_w1l[512 * 128];
__device__ __nv_bfloat16 g_wfh[512 * 1536], g_wfl[512 * 1536];
__device__ float g_wp2[512 * 1536], g_wp3[512 * 1536];
__device__ float g_bF[1500];
__device__ float g_sum[512], g_sumsq[512], g_alpha[512], g_delta[512];
__device__ float g_pcS[BATCH * 1500], g_pcQ[BATCH * 1500];
__device__ float g_pool[BATCH * 3000];
__device__ float g_fc1[BATCH * 512], g_fc1n[BATCH * 512], g_fc2[BATCH * 512];

// ---------------- prep / scalar kernels ----------------
__global__ void k_zero2(float* p, float* q, int n) {
    int i = blockIdx.x * blockDim.x + threadIdx.x;
    if (i < n) { p[i] = 0.f; q[i] = 0.f; }
}
__device__ __forceinline__ void split_st(float v, __nv_bfloat16* ph, __nv_bfloat16* pl) {
    __nv_bfloat16 h = __float2bfloat16(v);
    *ph = h;
    *pl = __float2bfloat16(v - __bfloat162float(h));
}
__global__ void k_presplice(const float* __restrict__ x, __nv_bfloat16* __restrict__ xh,
                            __nv_bfloat16* __restrict__ xl) {
    int i = blockIdx.x * blockDim.x + threadIdx.x;
    if (i >= N1 * 128) return;
    int r = i >> 7, kk = i & 127;
    float v = 0.f;
    if (kk < 100) {
        int c = kk / 20, f = kk - c * 20;
        int b = r / TT1, t = r - b * TT1;
        v = x[((size_t)(b * TT0 + t + c)) * 20 + f];
    }
    split_st(v, &xh[i], &xl[i]);
}
__global__ void k_prepw1(const float* __restrict__ w, __nv_bfloat16* __restrict__ wh,
                         __nv_bfloat16* __restrict__ wl) {
    int i = blockIdx.x * blockDim.x + threadIdx.x;
    if (i >= 512 * 128) return;
    int m = i >> 7, kk = i & 127;
    float v = 0.f;
    if (kk < 100) {
        int c = kk / 20, f = kk - c * 20;
        v = w[m * 100 + f * 5 + c];
    }
    split_st(v, &wh[i], &wl[i]);
}
__global__ void k_permMK(const float* __restrict__ w, float* __restrict__ wP) {
    int i = blockIdx.x * blockDim.x + threadIdx.x;
    if (i >= 512 * 1536) return;
    int m = i / 1536, kp = i - m * 1536;
    int c = kp >> 9, f = kp & 511;
    wP[i] = w[m * 1536 + f * 3 + c];
}
__global__ void k_bn_params(const float* __restrict__ sum, const float* __restrict__ sumsq,
                            float invN, const float* __restrict__ gamma,
                            const float* __restrict__ beta, int F,
                            float* __restrict__ alpha, float* __restrict__ delta) {
    int f = blockIdx.x * blockDim.x + threadIdx.x;
    if (f >= F) return;
    float mean = sum[f] * invN;
    float var = sumsq[f] * invN - mean * mean;
    float a = rsqrtf(var + 1e-5f) * (gamma ? gamma[f] : 1.f);
    alpha[f] = a;
    delta[f] = (beta ? beta[f] : 0.f) - mean * a;
}
__global__ void k_fold_split(const float* __restrict__ wP, const float* __restrict__ alpha,
                             int F, int K, int MK, __nv_bfloat16* __restrict__ wh,
                             __nv_bfloat16* __restrict__ wl) {
    int i = blockIdx.x * blockDim.x + threadIdx.x;
    if (i >= MK) return;
    int k = i % K;
    split_st(wP[i] * alpha[k % F], &wh[i], &wl[i]);
}
__global__ void k_fold_bias(const float* __restrict__ wP, const float* __restrict__ b0,
                            const float* __restrict__ delta, int F, int K, int M,
                            float* __restrict__ bF) {
    int m = blockIdx.x * blockDim.x + threadIdx.x;
    if (m >= M) return;
    float acc = b0[m];
    for (int k = 0; k < K; k++) acc += wP[(size_t)m * K + k] * delta[k % F];
    bF[m] = acc;
}
__global__ void k_pool(const float* __restrict__ pcS, const float* __restrict__ pcQ,
                       int T, int M, const float* __restrict__ gamma,
                       const float* __restrict__ beta, float* __restrict__ pooled) {
    int c = blockIdx.x * blockDim.x + threadIdx.x;
    if (c >= M) return;
    float gs = 0.f, gq = 0.f;
    for (int b = 0; b < BATCH; b++) { gs += pcS[b * M + c]; gq += pcQ[b * M + c]; }
    float Nf = (float)(BATCH * T);
    float mean = gs / Nf;
    float var = gq / Nf - mean * mean;
    float a = rsqrtf(var + 1e-5f) * gamma[c];
    float bt = beta[c];
    float Tf = (float)T;
    for (int b = 0; b < BATCH; b++) {
        float S1 = pcS[b * M + c], S2 = pcQ[b * M + c];
        float mt = S1 / Tf;
        float vt = (S2 - S1 * S1 / Tf) / (Tf - 1.f);
        pooled[b * 2 * M + c] = (mt - mean) * a + bt;
        pooled[b * 2 * M + M + c] = sqrtf(fmaxf(vt, 0.f)) * fabsf(a);
    }
}
__global__ void k_fc(const float* __restrict__ X, const float* __restrict__ W,
                     const float* __restrict__ bias, float* __restrict__ Y, int K, int M) {
    __shared__ float red[4][32];
    int m = blockIdx.x, tid = threadIdx.x;
    float acc[BATCH];
#pragma unroll
    for (int b = 0; b < BATCH; b++) acc[b] = 0.f;
    for (int k = tid; k < K; k += blockDim.x) {
        float w = W[(size_t)m * K + k];
#pragma unroll
        for (int b = 0; b < BATCH; b++) acc[b] += X[b * K + k] * w;
    }
#pragma unroll
    for (int b = 0; b < BATCH; b++) {
        float v = acc[b];
#pragma unroll
        for (int o = 16; o; o >>= 1) v += __shfl_down_sync(0xffffffffu, v, o);
        if ((tid & 31) == 0) red[tid >> 5][b] = v;
    }
    __syncthreads();
    if (tid < BATCH) {
        float v = red[0][tid] + red[1][tid] + red[2][tid] + red[3][tid] + bias[m];
        Y[tid * M + m] = fminf(fmaxf(v, 0.f), 6.f);
    }
}
__global__ void k_bnc(const float* __restrict__ X, const float* __restrict__ gamma,
                      const float* __restrict__ beta, float* __restrict__ Y, int M) {
    int j = blockIdx.x * blockDim.x + threadIdx.x;
    if (j >= M) return;
    float s = 0.f, q = 0.f;
    for (int b = 0; b < BATCH; b++) { float v = X[b * M + j]; s += v; q += v * v; }
    float mean = s / (float)BATCH;
    float var = q / (float)BATCH - mean * mean;
    float sc = rsqrtf(var + 1e-5f) * gamma[j];
    for (int b = 0; b < BATCH; b++) Y[b * M + j] = (X[b * M + j] - mean) * sc + beta[j];
}

// ---------------- HMMA GEMM (m16n8k16 bf16, hi/lo 3-product) ----------------
// C[128 x 256] per CTA, 8 warps as 2(row)x4(col), warp tile 64x64. BK=32,
// TRIPLE-buffered cp.async (wait_group 1 steady state). SMEM stage (48KB):
// Ah@0 Al@8192 Wh@16384 Wl@32768. Fused epilogue stats; outH==nullptr -> stats-only.
__device__ __forceinline__ uint32_t smem_u32(const void* p) {
    uint32_t a;
    asm("{ .reg .u64 t; cvta.to.shared.u64 t, %1; cvt.u32.u64 %0, t; }" : "=r"(a) : "l"(p));
    return a;
}
__device__ __forceinline__ void cpa(uint32_t dst, const void* src, uint32_t n) {
    asm volatile("cp.async.cg.shared.global [%0], [%1], 16, %2;" :: "r"(dst), "l"(src), "r"(n) : "memory");
}
#define LDM4(v, a) \
    asm volatile("ldmatrix.sync.aligned.m8n8.x4.shared.b16 {%0,%1,%2,%3}, [%4];" \
        : "=r"((v)[0]), "=r"((v)[1]), "=r"((v)[2]), "=r"((v)[3]) : "r"(a))
#define MMA(d, a, b0, b1) \
    asm volatile("mma.sync.aligned.m16n8k16.row.col.f32.bf16.bf16.f32 " \
        "{%0,%1,%2,%3}, {%4,%5,%6,%7}, {%8,%9}, {%0,%1,%2,%3};" \
        : "+f"((d)[0]), "+f"((d)[1]), "+f"((d)[2]), "+f"((d)[3]) \
        : "r"((a)[0]), "r"((a)[1]), "r"((a)[2]), "r"((a)[3]), "r"(b0), "r"(b1))

#define STG_SZ 49152
#define NSTG 3

__global__ __launch_bounds__(256)
void mma_gemm(const __nv_bfloat16* __restrict__ inH, const __nv_bfloat16* __restrict__ inL,
              const __nv_bfloat16* __restrict__ wH, const __nv_bfloat16* __restrict__ wL,
              const float* __restrict__ bias,
              __nv_bfloat16* __restrict__ outH, __nv_bfloat16* __restrict__ outL,
              float* __restrict__ statS, float* __restrict__ statQ,
              int statT, int statStride,
              int Tin, int Tout, int F, int step,
              int Ktot, int Mtot, int Mstride, int Nrows, float actmax) {
    extern __shared__ char smem[];
    const uint32_t sb = smem_u32(smem);
    const int t = threadIdx.x;
    const int row0 = blockIdx.y * 128;
    const int colbase = blockIdx.x * 256;
    const int NKC = Ktot >> 5, FC = F >> 5;

    // ---- loader mapping ----
    const int lr = t >> 2, kg = t & 3;
    int ra = row0 + lr, rb = row0 + lr + 64;
    bool va = ra < Nrows, vb = rb < Nrows;
    size_t aba = 0, abb = 0;
    if (va) { int b_ = ra / Tout; aba = (size_t)(b_ * Tin + (ra - b_ * Tout)) * F; }
    if (vb) { int b_ = rb / Tout; abb = (size_t)(b_ * Tin + (rb - b_ * Tout)) * F; }
    const uint32_t swz = (uint32_t)((kg ^ ((lr >> 1) & 3)) << 4);
    const uint32_t dA0 = sb + lr * 64 + swz;
    const uint32_t dA1 = sb + (lr + 64) * 64 + swz;
    uint32_t vA0 = va ? 16u : 0u, vA1 = vb ? 16u : 0u;
    size_t wb[4]; uint32_t vW[4], dW[4];
#pragma unroll
    for (int j = 0; j < 4; j++) {
        int n = colbase + lr + 64 * j;
        bool ok = n < Mtot;
        vW[j] = ok ? 16u : 0u;
        wb[j] = ok ? (size_t)n * Ktot : 0;
        dW[j] = sb + 16384 + (lr + 64 * j) * 64 + swz;
    }

#define LOAD_CHUNK(kc, stg) do { \
        uint32_t bo = (uint32_t)(stg) * STG_SZ; \
        int c_ = (kc) / FC; \
        size_t ao = (size_t)c_ * step * F + (size_t)((kc) - c_ * FC) * 32 + kg * 8; \
        size_t wo = (size_t)(kc) * 32 + kg * 8; \
        cpa(dA0 + bo,        inH + aba + ao, vA0); \
        cpa(dA1 + bo,        inH + abb + ao, vA1); \
        cpa(dA0 + 8192 + bo, inL + aba + ao, vA0); \
        cpa(dA1 + 8192 + bo, inL + abb + ao, vA1); \
        _Pragma("unroll") \
        for (int j = 0; j < 4; j++) { \
            cpa(dW[j] + bo,         wH + wb[j] + wo, vW[j]); \
            cpa(dW[j] + 16384 + bo, wL + wb[j] + wo, vW[j]); \
        } \
        asm volatile("cp.async.commit_group;" ::: "memory"); \
    } while (0)

    // ---- compute mapping ----
    const int wid = t >> 5, lane = t & 31;
    const int wr = wid & 1, wc = wid >> 1;
    uint32_t aAd[4], wAd[4];
    {
        int rbase = wr * 64 + (lane & 15);
        int kg0 = lane >> 4;
#pragma unroll
        for (int mi = 0; mi < 4; mi++) {
            int rr = rbase + mi * 16;
            aAd[mi] = sb + rr * 64 + ((kg0 ^ ((rr >> 1) & 3)) << 4);
        }
        int kgw = (lane >> 3) & 1;
#pragma unroll
        for (int cj = 0; cj < 4; cj++) {
            int nn = wc * 64 + cj * 16 + (lane & 7) + ((lane >> 4) << 3);
            wAd[cj] = sb + 16384 + nn * 64 + ((kgw ^ ((nn >> 1) & 3)) << 4);
        }
    }

    float acc[4][8][4];
#pragma unroll
    for (int i = 0; i < 4; i++)
#pragma unroll
        for (int j = 0; j < 8; j++)
#pragma unroll
            for (int q = 0; q < 4; q++) acc[i][j][q] = 0.f;

    // prologue: 2 chunks in flight
    LOAD_CHUNK(0, 0);
    if (NKC > 1) LOAD_CHUNK(1, 1);
    int stg = 0, nstg = (NKC > 1) ? 2 : 1;
    for (int kc = 0; kc < NKC; kc++) {
        if (kc + 1 < NKC) asm volatile("cp.async.wait_group 1;" ::: "memory");
        else              asm volatile("cp.async.wait_group 0;" ::: "memory");
        __syncthreads();
        if (kc + 2 < NKC) {
            LOAD_CHUNK(kc + 2, nstg);
            nstg = (nstg == NSTG - 1) ? 0 : nstg + 1;
        }
        uint32_t bo = (uint32_t)stg * STG_SZ;
        stg = (stg == NSTG - 1) ? 0 : stg + 1;
#pragma unroll
        for (int ks = 0; ks < 2; ks++) {
            uint32_t kx = (uint32_t)ks << 5;
            uint32_t ah[4][4], al[4][4];
#pragma unroll
            for (int mi = 0; mi < 4; mi++) {
                uint32_t ad = (aAd[mi] ^ kx) + bo;
                LDM4(ah[mi], ad);
                LDM4(al[mi], ad + 8192);
            }
#pragma unroll
            for (int cj = 0; cj < 4; cj++) {
                uint32_t wh[4], wl[4];
                uint32_t ad = (wAd[cj] ^ kx) + bo;
                LDM4(wh, ad);
                LDM4(wl, ad + 16384);
#pragma unroll
                for (int mi = 0; mi < 4; mi++) {
#pragma unroll
                    for (int njl = 0; njl < 2; njl++) {
                        int nj = cj * 2 + njl, h = njl << 1;
                        MMA(acc[mi][nj], ah[mi], wh[h], wh[h + 1]);
                        MMA(acc[mi][nj], ah[mi], wl[h], wl[h + 1]);
                        MMA(acc[mi][nj], al[mi], wh[h], wh[h + 1]);
                    }
                }
            }
        }
    }

    // ---- fused epilogue ----
    const int re = row0 + wr * 64 + (lane >> 2);
    const int ce = colbase + wc * 64 + ((lane & 3) << 1);
    const bool wantOut = (outH != nullptr);
    const int rb0 = row0 + wr * 64;
    const bool anyrow = rb0 < Nrows;
    const int rfirst = anyrow ? rb0 : 0;
    const int rlast = min(rb0 + 63, Nrows - 1);
    const int bb0 = rfirst / statT;
    const int bb1 = (rlast >= 0) ? (rlast / statT) : bb0;
    const int rsplit = (bb0 + 1) * statT;

#pragma unroll
    for (int nj = 0; nj < 8; nj++) {
        int m = ce + nj * 8;
        bool mok = (m < Mtot);
        float s0x = 0.f, s0y = 0.f, q0x = 0.f, q0y = 0.f;
        float s1x = 0.f, s1y = 0.f, q1x = 0.f, q1y = 0.f;
        if (mok) {
            float b0v = bias[m], b1v = bias[m + 1];
#pragma unroll
            for (int mi = 0; mi < 4; mi++) {
#pragma unroll
                for (int half = 0; half < 2; half++) {
                    int r = re + mi * 16 + half * 8;
                    if (r >= Nrows) continue;
                    float v0 = fminf(fmaxf(acc[mi][nj][half * 2] + b0v, 0.f), actmax);
                    float v1 = fminf(fmaxf(acc[mi][nj][half * 2 + 1] + b1v, 0.f), actmax);
                    if (r >= rsplit) { s1x += v0; q1x += v0 * v0; s1y += v1; q1y += v1 * v1; }
                    else            { s0x += v0; q0x += v0 * v0; s0y += v1; q0y += v1 * v1; }
                    if (wantOut) {
                        __nv_bfloat16 h0 = __float2bfloat16(v0), h1 = __float2bfloat16(v1);
                        __nv_bfloat16 l0 = __float2bfloat16(v0 - __bfloat162float(h0));
                        __nv_bfloat16 l1 = __float2bfloat16(v1 - __bfloat162float(h1));
                        size_t ob = (size_t)r * Mstride + m;
                        *(__nv_bfloat162*)(outH + ob) = __halves2bfloat162(h0, h1);
                        *(__nv_bfloat162*)(outL + ob) = __halves2bfloat162(l0, l1);
                    }
                }
            }
        }
#pragma unroll
        for (int o = 4; o <= 16; o <<= 1) {
            s0x += __shfl_xor_sync(0xffffffffu, s0x, o);
            s0y += __shfl_xor_sync(0xffffffffu, s0y, o);
            q0x += __shfl_xor_sync(0xffffffffu, q0x, o);
            q0y += __shfl_xor_sync(0xffffffffu, q0y, o);
            s1x += __shfl_xor_sync(0xffffffffu, s1x, o);
            s1y += __shfl_xor_sync(0xffffffffu, s1y, o);
            q1x += __shfl_xor_sync(0xffffffffu, q1x, o);
            q1y += __shfl_xor_sync(0xffffffffu, q1y, o);
        }
        if (lane < 4 && anyrow) {
            int mm = colbase + wc * 64 + (lane << 1) + nj * 8;
            if (mm < Mtot) {
                int i0 = bb0 * statStride + mm;
                atomicAdd(&statS[i0], s0x);
                atomicAdd(&statS[i0 + 1], s0y);
                atomicAdd(&statQ[i0], q0x);
                atomicAdd(&statQ[i0 + 1], q0y);
                if (bb1 != bb0) {
                    int i1 = bb1 * statStride + mm;
                    atomicAdd(&statS[i1], s1x);
                    atomicAdd(&statS[i1 + 1], s1y);
                    atomicAdd(&statQ[i1], q1x);
                    atomicAdd(&statQ[i1 + 1], q1y);
                }
            }
        }
    }
#undef LOAD_CHUNK
}

// ---------------------------------------------------------------------------
extern "C" void kernel_launch(void* const* d_in, const int* in_sizes, int n_in,
                              void* d_out, int out_size) {
    (void)in_sizes; (void)n_in; (void)out_size;
    const float* x    = (const float*)d_in[0];
    const float* h1_w = (const float*)d_in[1];  const float* h1_b = (const float*)d_in[2];
    const float* h2_w = (const float*)d_in[3];  const float* h2_b = (const float*)d_in[4];
    const float* bn2g = (const float*)d_in[5];  const float* bn2b = (const float*)d_in[6];
    const float* h3_w = (const float*)d_in[7];  const float* h3_b = (const float*)d_in[8];
    const float* bn3g = (const float*)d_in[9];  const float* bn3b = (const float*)d_in[10];
    const float* h4_w = (const float*)d_in[11]; const float* h4_b = (const float*)d_in[12];
    const float* bn4g = (const float*)d_in[13]; const float* bn4b = (const float*)d_in[14];
    const float* h5_w = (const float*)d_in[15]; const float* h5_b = (const float*)d_in[16];
    const float* bn5g = (const float*)d_in[17]; const float* bn5b = (const float*)d_in[18];
    const float* l1_w = (const float*)d_in[19]; const float* l1_b = (const float*)d_in[20];
    const float* bn6g = (const float*)d_in[21]; const float* bn6b = (const float*)d_in[22];
    const float* l2_w = (const float*)d_in[23]; const float* l2_b = (const float*)d_in[24];
    const float* bn7g = (const float*)d_in[25]; const float* bn7b = (const float*)d_in[26];

    __nv_bfloat16 *xsh, *xsl, *aH0, *aL0, *aH1, *aL1, *w1h, *w1l, *wfh, *wfl;
    float *wp2, *wp3, *bF, *sumP, *sumsqP, *alphaP, *deltaP, *pcS, *pcQ, *pool, *fc1, *fc1n, *fc2;
    cudaGetSymbolAddress((void**)&xsh, g_xsh);   cudaGetSymbolAddress((void**)&xsl, g_xsl);
    cudaGetSymbolAddress((void**)&aH0, g_aH0);   cudaGetSymbolAddress((void**)&aL0, g_aL0);
    cudaGetSymbolAddress((void**)&aH1, g_aH1);   cudaGetSymbolAddress((void**)&aL1, g_aL1);
    cudaGetSymbolAddress((void**)&w1h, g_w1h);   cudaGetSymbolAddress((void**)&w1l, g_w1l);
    cudaGetSymbolAddress((void**)&wfh, g_wfh);   cudaGetSymbolAddress((void**)&wfl, g_wfl);
    cudaGetSymbolAddress((void**)&wp2, g_wp2);   cudaGetSymbolAddress((void**)&wp3, g_wp3);
    cudaGetSymbolAddress((void**)&bF, g_bF);
    cudaGetSymbolAddress((void**)&sumP, g_sum);  cudaGetSymbolAddress((void**)&sumsqP, g_sumsq);
    cudaGetSymbolAddress((void**)&alphaP, g_alpha); cudaGetSymbolAddress((void**)&deltaP, g_delta);
    cudaGetSymbolAddress((void**)&pcS, g_pcS);   cudaGetSymbolAddress((void**)&pcQ, g_pcQ);
    cudaGetSymbolAddress((void**)&pool, g_pool);
    cudaGetSymbolAddress((void**)&fc1, g_fc1);   cudaGetSymbolAddress((void**)&fc1n, g_fc1n);
    cudaGetSymbolAddress((void**)&fc2, g_fc2);

    cudaFuncSetAttribute(mma_gemm, cudaFuncAttributeMaxDynamicSharedMemorySize, NSTG * STG_SZ);
    const float BIG = 3.0e38f;

    // prep — ordered so launch #6 (ncu -s 5 -c 1 capture slot) is mma_gemm stage 1
    k_presplice<<<(N1 * 128 + 255) / 256, 256>>>(x, xsh, xsl);          // 1
    k_prepw1<<<(512 * 128 + 255) / 256, 256>>>(h1_w, w1h, w1l);         // 2
    k_zero2<<<2, 256>>>(sumP, sumsqP, 512);                              // 3
    k_permMK<<<(512 * 1536 + 255) / 256, 256>>>(h2_w, wp2);             // 4
    k_permMK<<<(512 * 1536 + 255) / 256, 256>>>(h3_w, wp3);             // 5

    // stage 1: K=128 (padded), M=512, relu; fused bn1 stats               6
    { dim3 g(2, N1 / 128);
      mma_gemm<<<g, 256, NSTG * STG_SZ>>>(xsh, xsl, w1h, w1l, h1_b, aH0, aL0,
                                          sumP, sumsqP, N1, 0,
                                          TT1, TT1, 128, 0, 128, 512, 512, N1, BIG); }
    k_bn_params<<<2, 256>>>(sumP, sumsqP, 1.f / (float)N1, nullptr, nullptr, 512, alphaP, deltaP);
    k_fold_split<<<(512 * 1536 + 255) / 256, 256>>>(wp2, alphaP, 512, 1536, 512 * 1536, wfh, wfl);
    k_fold_bias<<<2, 256>>>(wp2, h2_b, deltaP, 512, 1536, 512, bF);

    // stage 2: K=1536 (3x512, step 2), M=512, relu; fused bn2 stats
    k_zero2<<<2, 256>>>(sumP, sumsqP, 512);
    { dim3 g(2, N2 / 128);
      mma_gemm<<<g, 256, NSTG * STG_SZ>>>(aH0, aL0, wfh, wfl, bF, aH1, aL1,
                                          sumP, sumsqP, N2, 0,
                                          TT1, TT2, 512, 2, 1536, 512, 512, N2, BIG); }
    k_bn_params<<<2, 256>>>(sumP, sumsqP, 1.f / (float)N2, bn2g, bn2b, 512, alphaP, deltaP);
    k_fold_split<<<(512 * 1536 + 255) / 256, 256>>>(wp3, alphaP, 512, 1536, 512 * 1536, wfh, wfl);
    k_fold_bias<<<2, 256>>>(wp3, h3_b, deltaP, 512, 1536, 512, bF);

    // stage 3: K=1536 (3x512, step 3), M=512, relu; fused bn3 stats
    k_zero2<<<2, 256>>>(sumP, sumsqP, 512);
    { dim3 g(2, (N3 + 127) / 128);
      mma_gemm<<<g, 256, NSTG * STG_SZ>>>(aH1, aL1, wfh, wfl, bF, aH0, aL0,
                                          sumP, sumsqP, N3, 0,
                                          TT2, TT3, 512, 3, 1536, 512, 512, N3, BIG); }
    k_bn_params<<<2, 256>>>(sumP, sumsqP, 1.f / (float)N3, bn3g, bn3b, 512, alphaP, deltaP);
    k_fold_split<<<(512 * 512 + 255) / 256, 256>>>(h4_w, alphaP, 512, 512, 512 * 512, wfh, wfl);
    k_fold_bias<<<2, 256>>>(h4_w, h4_b, deltaP, 512, 512, 512, bF);

    // stage 4: K=512, M=512, relu6; fused bn4 stats
    k_zero2<<<2, 256>>>(sumP, sumsqP, 512);
    { dim3 g(2, (N3 + 127) / 128);
      mma_gemm<<<g, 256, NSTG * STG_SZ>>>(aH0, aL0, wfh, wfl, bF, aH1, aL1,
                                          sumP, sumsqP, N3, 0,
                                          TT3, TT3, 512, 0, 512, 512, 512, N3, 6.f); }
    k_bn_params<<<2, 256>>>(sumP, sumsqP, 1.f / (float)N3, bn4g, bn4b, 512, alphaP, deltaP);
    k_fold_split<<<(1500 * 512 + 255) / 256, 256>>>(h5_w, alphaP, 512, 512, 1500 * 512, wfh, wfl);
    k_fold_bias<<<(1500 + 255) / 256, 256>>>(h5_w, h5_b, deltaP, 512, 512, 1500, bF);

    // stage 5: K=512, M=1500, relu6 — stats-only, per-(b,c)
    k_zero2<<<(BATCH * 1500 + 255) / 256, 256>>>(pcS, pcQ, BATCH * 1500);
    { dim3 g(6, (N3 + 127) / 128);
      mma_gemm<<<g, 256, NSTG * STG_SZ>>>(aH1, aL1, wfh, wfl, bF, nullptr, nullptr,
                                          pcS, pcQ, TT3, 1500,
                                          TT3, TT3, 512, 0, 512, 1500, 1500, N3, 6.f); }
    k_pool<<<(1500 + 255) / 256, 256>>>(pcS, pcQ, TT3, 1500, bn5g, bn5b, pool);

    // FC head
    k_fc<<<512, 128>>>(pool, l1_w, l1_b, fc1, 3000, 512);
    k_bnc<<<2, 256>>>(fc1, bn6g, bn6b, fc1n, 512);
    k_fc<<<512, 128>>>(fc1n, l2_w, l2_b, fc2, 512, 512);
    k_bnc<<<2, 256>>>(fc2, bn7g, bn7b, (float*)d_out, 512);
}